// round 1
// baseline (speedup 1.0000x reference)
#include <cuda_runtime.h>

#define BB 4
#define NSEQ 2048
#define CDIM 768
#define HNUM 12
#define DHEAD 64
#define QK_SCALE 0.125f

// ---------------- scratch (device globals; no allocations allowed) -------
__device__ float g_q[BB * HNUM * NSEQ * DHEAD];
__device__ float g_k[BB * HNUM * NSEQ * DHEAD];
__device__ float g_v[BB * HNUM * NSEQ * DHEAD];
__device__ float g_ctx[BB * NSEQ * CDIM];
__device__ unsigned g_maskbits[NSEQ * (NSEQ / 32)];   // [2048][64] bit-packed
__device__ int g_mask_mode;                            // 0=int32, 1=float32, 2=uint8

// ---------------- mask encoding probe ------------------------------------
__global__ void probe_mask(const unsigned* __restrict__ mw) {
    __shared__ int s_not01, s_notfloat;
    int tid = threadIdx.x;
    if (tid == 0) { s_not01 = 0; s_notfloat = 0; }
    __syncthreads();
    unsigned v = mw[tid];                  // first 256 words (>=1KB always valid)
    if (v != 0u && v != 1u) s_not01 = 1;
    if (v != 0u && v != 0x3F800000u) s_notfloat = 1;
    __syncthreads();
    if (tid == 0) g_mask_mode = (!s_not01) ? 0 : (!s_notfloat ? 1 : 2);
}

__global__ void mask_pack(const void* __restrict__ mask) {
    int gid = blockIdx.x * 256 + threadIdx.x;          // 2048*64 words
    if (gid >= NSEQ * (NSEQ / 32)) return;
    int i = gid >> 6;
    int w = gid & 63;
    long base = (long)i * NSEQ + (long)w * 32;
    int mode = g_mask_mode;
    unsigned bits = 0u;
    if (mode == 0) {
        const int* p = (const int*)mask;
        #pragma unroll
        for (int j = 0; j < 32; j++) if (p[base + j] != 0) bits |= (1u << j);
    } else if (mode == 1) {
        const float* p = (const float*)mask;
        #pragma unroll
        for (int j = 0; j < 32; j++) if (p[base + j] != 0.0f) bits |= (1u << j);
    } else {
        const unsigned char* p = (const unsigned char*)mask;
        #pragma unroll
        for (int j = 0; j < 32; j++) if (p[base + j] != 0) bits |= (1u << j);
    }
    g_maskbits[gid] = bits;
}

// ---------------- GEMM 1: qkv = x @ w_qkv, scatter to q/k/v --------------
// x: [8192, 768], w: [768, 2304]. 128x128 tile, 256 thr, 8x8 per thread.
__global__ __launch_bounds__(256) void qkv_gemm(const float* __restrict__ X,
                                                const float* __restrict__ W) {
    __shared__ float As[8][128];
    __shared__ float Bs[8][128];
    int tid = threadIdx.x;
    int tx = tid & 15, ty = tid >> 4;
    int m0 = blockIdx.y * 128, n0 = blockIdx.x * 128;
    int a_row = tid >> 1, a_k = (tid & 1) * 4;
    int b_row = tid >> 5, b_c = (tid & 31) * 4;
    float acc[8][8];
    #pragma unroll
    for (int i = 0; i < 8; i++)
        #pragma unroll
        for (int j = 0; j < 8; j++) acc[i][j] = 0.0f;

    for (int k0 = 0; k0 < 768; k0 += 8) {
        float4 av = *(const float4*)(X + (long)(m0 + a_row) * 768 + k0 + a_k);
        float4 bv = *(const float4*)(W + (long)(k0 + b_row) * 2304 + n0 + b_c);
        __syncthreads();
        As[a_k + 0][a_row] = av.x;
        As[a_k + 1][a_row] = av.y;
        As[a_k + 2][a_row] = av.z;
        As[a_k + 3][a_row] = av.w;
        *(float4*)&Bs[b_row][b_c] = bv;
        __syncthreads();
        #pragma unroll
        for (int kk = 0; kk < 8; kk++) {
            float a[8], b[8];
            float4 t0 = *(const float4*)&As[kk][ty * 8];
            float4 t1 = *(const float4*)&As[kk][ty * 8 + 4];
            a[0]=t0.x; a[1]=t0.y; a[2]=t0.z; a[3]=t0.w;
            a[4]=t1.x; a[5]=t1.y; a[6]=t1.z; a[7]=t1.w;
            float4 u0 = *(const float4*)&Bs[kk][tx * 8];
            float4 u1 = *(const float4*)&Bs[kk][tx * 8 + 4];
            b[0]=u0.x; b[1]=u0.y; b[2]=u0.z; b[3]=u0.w;
            b[4]=u1.x; b[5]=u1.y; b[6]=u1.z; b[7]=u1.w;
            #pragma unroll
            for (int i = 0; i < 8; i++)
                #pragma unroll
                for (int j = 0; j < 8; j++) acc[i][j] = fmaf(a[i], b[j], acc[i][j]);
        }
    }
    // scatter: n in [0,2304): which = n/768, h = (n%768)/64, d = n%64
    int nb = n0 + tx * 8;                 // 8-aligned -> never crosses 64 boundary
    int which = nb / 768;
    int rem = nb - which * 768;
    int h = rem >> 6;
    int d0 = rem & 63;
    float* dst = (which == 0) ? g_q : ((which == 1) ? g_k : g_v);
    #pragma unroll
    for (int i = 0; i < 8; i++) {
        int m = m0 + ty * 8 + i;
        int b_ = m >> 11, ii = m & 2047;
        float* p = dst + ((((long)b_ * HNUM + h) * NSEQ + ii) * DHEAD + d0);
        *(float4*)p       = make_float4(acc[i][0], acc[i][1], acc[i][2], acc[i][3]);
        *(float4*)(p + 4) = make_float4(acc[i][4], acc[i][5], acc[i][6], acc[i][7]);
    }
}

// ---------------- flash attention -----------------------------------------
// grid: (16 q-tiles, 48 bh). 128 threads, 8x8 micro-tiles.
#define SM_QT 0
#define SM_KT (64 * 132)
#define SM_VS (SM_KT + 64 * 68)
#define SM_PT (SM_VS + 64 * 68)
#define SM_MS (SM_PT + 64 * 132)
#define ATTN_SMEM_BYTES ((SM_MS) * 4 + 128 * 2 * 4)

__global__ __launch_bounds__(128) void attn_kernel() {
    extern __shared__ float sm[];
    float* Qt = sm + SM_QT;     // [64 d][132] rows of 128 queries (+pad)
    float* Kt = sm + SM_KT;     // [64 d][68] keys
    float* Vs = sm + SM_VS;     // [64 key][68] dims
    float* Pt = sm + SM_PT;     // [64 key][132] rows
    unsigned* Ms = (unsigned*)(sm + SM_MS);   // [128 rows][2 words]

    int tid = threadIdx.x;
    int tx = tid & 7, ty = tid >> 3;
    int bh = blockIdx.y;
    int b = bh / HNUM, h = bh - b * HNUM;
    int row0 = blockIdx.x * 128;
    const float* qg = g_q + (long)bh * NSEQ * DHEAD;
    const float* kg = g_k + (long)bh * NSEQ * DHEAD;
    const float* vg = g_v + (long)bh * NSEQ * DHEAD;

    // load Q tile (transposed, pre-scaled)
    #pragma unroll
    for (int r = 0; r < 16; r++) {
        int q4 = r * 128 + tid;
        int row = q4 >> 4;
        int d = (q4 & 15) * 4;
        float4 v = *(const float4*)(qg + (long)(row0 + row) * DHEAD + d);
        Qt[(d + 0) * 132 + row] = v.x * QK_SCALE;
        Qt[(d + 1) * 132 + row] = v.y * QK_SCALE;
        Qt[(d + 2) * 132 + row] = v.z * QK_SCALE;
        Qt[(d + 3) * 132 + row] = v.w * QK_SCALE;
    }

    float O[8][8];
    float mrow[8], lrow[8];
    #pragma unroll
    for (int i = 0; i < 8; i++) {
        mrow[i] = -1e30f; lrow[i] = 0.0f;
        #pragma unroll
        for (int j = 0; j < 8; j++) O[i][j] = 0.0f;
    }

    for (int t = 0; t < 32; t++) {
        int key0 = t * 64;
        __syncthreads();   // previous PV done before overwriting K/V/M
        #pragma unroll
        for (int r = 0; r < 8; r++) {
            int q4 = r * 128 + tid;
            int key = q4 >> 4;
            int d = (q4 & 15) * 4;
            float4 kv = *(const float4*)(kg + (long)(key0 + key) * DHEAD + d);
            Kt[(d + 0) * 68 + key] = kv.x;
            Kt[(d + 1) * 68 + key] = kv.y;
            Kt[(d + 2) * 68 + key] = kv.z;
            Kt[(d + 3) * 68 + key] = kv.w;
            float4 vv = *(const float4*)(vg + (long)(key0 + key) * DHEAD + d);
            *(float4*)&Vs[key * 68 + d] = vv;
        }
        {
            const unsigned* mp = g_maskbits + (long)(row0 + tid) * 64 + t * 2;
            Ms[tid * 2 + 0] = mp[0];
            Ms[tid * 2 + 1] = mp[1];
        }
        __syncthreads();

        // S = Q K^T  (scaled already)
        float s[8][8];
        #pragma unroll
        for (int i = 0; i < 8; i++)
            #pragma unroll
            for (int j = 0; j < 8; j++) s[i][j] = 0.0f;
        #pragma unroll 4
        for (int d = 0; d < 64; d++) {
            float a[8], bv[8];
            float4 t0 = *(const float4*)&Qt[d * 132 + ty * 8];
            float4 t1 = *(const float4*)&Qt[d * 132 + ty * 8 + 4];
            a[0]=t0.x; a[1]=t0.y; a[2]=t0.z; a[3]=t0.w;
            a[4]=t1.x; a[5]=t1.y; a[6]=t1.z; a[7]=t1.w;
            float4 u0 = *(const float4*)&Kt[d * 68 + tx * 8];
            float4 u1 = *(const float4*)&Kt[d * 68 + tx * 8 + 4];
            bv[0]=u0.x; bv[1]=u0.y; bv[2]=u0.z; bv[3]=u0.w;
            bv[4]=u1.x; bv[5]=u1.y; bv[6]=u1.z; bv[7]=u1.w;
            #pragma unroll
            for (int i = 0; i < 8; i++)
                #pragma unroll
                for (int j = 0; j < 8; j++) s[i][j] = fmaf(a[i], bv[j], s[i][j]);
        }

        // mask + online softmax (8 tx-lanes per row group share rows; same warp)
        int wsel = (tx >> 2) & 1;
        int bit0 = (tx & 3) * 8;
        #pragma unroll
        for (int i = 0; i < 8; i++) {
            unsigned mw = Ms[(ty * 8 + i) * 2 + wsel];
            float tmax = -1e30f;
            #pragma unroll
            for (int j = 0; j < 8; j++) {
                if ((mw >> (bit0 + j)) & 1u) s[i][j] = -1e30f;
                tmax = fmaxf(tmax, s[i][j]);
            }
            tmax = fmaxf(tmax, __shfl_xor_sync(0xffffffffu, tmax, 1));
            tmax = fmaxf(tmax, __shfl_xor_sync(0xffffffffu, tmax, 2));
            tmax = fmaxf(tmax, __shfl_xor_sync(0xffffffffu, tmax, 4));
            float mnew = fmaxf(mrow[i], tmax);
            float alpha = __expf(mrow[i] - mnew);
            mrow[i] = mnew;
            float lsum = 0.0f;
            #pragma unroll
            for (int j = 0; j < 8; j++) {
                float p = __expf(s[i][j] - mnew);
                s[i][j] = p;
                lsum += p;
            }
            lsum += __shfl_xor_sync(0xffffffffu, lsum, 1);
            lsum += __shfl_xor_sync(0xffffffffu, lsum, 2);
            lsum += __shfl_xor_sync(0xffffffffu, lsum, 4);
            lrow[i] = lrow[i] * alpha + lsum;
            #pragma unroll
            for (int j = 0; j < 8; j++) O[i][j] *= alpha;
        }

        // stage P transposed for the PV GEMM
        #pragma unroll
        for (int j = 0; j < 8; j++)
            #pragma unroll
            for (int i = 0; i < 8; i++)
                Pt[(tx * 8 + j) * 132 + ty * 8 + i] = s[i][j];
        __syncthreads();

        // O += P @ V
        #pragma unroll 4
        for (int k = 0; k < 64; k++) {
            float a[8], bv[8];
            float4 t0 = *(const float4*)&Pt[k * 132 + ty * 8];
            float4 t1 = *(const float4*)&Pt[k * 132 + ty * 8 + 4];
            a[0]=t0.x; a[1]=t0.y; a[2]=t0.z; a[3]=t0.w;
            a[4]=t1.x; a[5]=t1.y; a[6]=t1.z; a[7]=t1.w;
            float4 u0 = *(const float4*)&Vs[k * 68 + tx * 8];
            float4 u1 = *(const float4*)&Vs[k * 68 + tx * 8 + 4];
            bv[0]=u0.x; bv[1]=u0.y; bv[2]=u0.z; bv[3]=u0.w;
            bv[4]=u1.x; bv[5]=u1.y; bv[6]=u1.z; bv[7]=u1.w;
            #pragma unroll
            for (int i = 0; i < 8; i++)
                #pragma unroll
                for (int j = 0; j < 8; j++) O[i][j] = fmaf(a[i], bv[j], O[i][j]);
        }
    }

    // epilogue: normalize, write to ctx in [B, N, C] layout
    #pragma unroll
    for (int i = 0; i < 8; i++) {
        float inv = 1.0f / lrow[i];
        int row = row0 + ty * 8 + i;
        float* dst = g_ctx + ((long)b * NSEQ + row) * CDIM + h * DHEAD + tx * 8;
        *(float4*)dst       = make_float4(O[i][0]*inv, O[i][1]*inv, O[i][2]*inv, O[i][3]*inv);
        *(float4*)(dst + 4) = make_float4(O[i][4]*inv, O[i][5]*inv, O[i][6]*inv, O[i][7]*inv);
    }
}

// ---------------- GEMM 2: out = ctx @ w_proj + b_proj ---------------------
__global__ __launch_bounds__(256) void proj_gemm(const float* __restrict__ W,
                                                 const float* __restrict__ Bias,
                                                 float* __restrict__ Out) {
    __shared__ float As[8][128];
    __shared__ float Bs[8][128];
    int tid = threadIdx.x;
    int tx = tid & 15, ty = tid >> 4;
    int m0 = blockIdx.y * 128, n0 = blockIdx.x * 128;
    int a_row = tid >> 1, a_k = (tid & 1) * 4;
    int b_row = tid >> 5, b_c = (tid & 31) * 4;
    float acc[8][8];
    #pragma unroll
    for (int i = 0; i < 8; i++)
        #pragma unroll
        for (int j = 0; j < 8; j++) acc[i][j] = 0.0f;

    for (int k0 = 0; k0 < 768; k0 += 8) {
        float4 av = *(const float4*)(g_ctx + (long)(m0 + a_row) * 768 + k0 + a_k);
        float4 bv = *(const float4*)(W + (long)(k0 + b_row) * 768 + n0 + b_c);
        __syncthreads();
        As[a_k + 0][a_row] = av.x;
        As[a_k + 1][a_row] = av.y;
        As[a_k + 2][a_row] = av.z;
        As[a_k + 3][a_row] = av.w;
        *(float4*)&Bs[b_row][b_c] = bv;
        __syncthreads();
        #pragma unroll
        for (int kk = 0; kk < 8; kk++) {
            float a[8], b[8];
            float4 t0 = *(const float4*)&As[kk][ty * 8];
            float4 t1 = *(const float4*)&As[kk][ty * 8 + 4];
            a[0]=t0.x; a[1]=t0.y; a[2]=t0.z; a[3]=t0.w;
            a[4]=t1.x; a[5]=t1.y; a[6]=t1.z; a[7]=t1.w;
            float4 u0 = *(const float4*)&Bs[kk][tx * 8];
            float4 u1 = *(const float4*)&Bs[kk][tx * 8 + 4];
            b[0]=u0.x; b[1]=u0.y; b[2]=u0.z; b[3]=u0.w;
            b[4]=u1.x; b[5]=u1.y; b[6]=u1.z; b[7]=u1.w;
            #pragma unroll
            for (int i = 0; i < 8; i++)
                #pragma unroll
                for (int j = 0; j < 8; j++) acc[i][j] = fmaf(a[i], b[j], acc[i][j]);
        }
    }
    float bj[8];
    #pragma unroll
    for (int j = 0; j < 8; j++) bj[j] = Bias[n0 + tx * 8 + j];
    #pragma unroll
    for (int i = 0; i < 8; i++) {
        int m = m0 + ty * 8 + i;
        float* p = Out + (long)m * 768 + n0 + tx * 8;
        *(float4*)p       = make_float4(acc[i][0]+bj[0], acc[i][1]+bj[1],
                                        acc[i][2]+bj[2], acc[i][3]+bj[3]);
        *(float4*)(p + 4) = make_float4(acc[i][4]+bj[4], acc[i][5]+bj[5],
                                        acc[i][6]+bj[6], acc[i][7]+bj[7]);
    }
}

// ---------------- launch ---------------------------------------------------
extern "C" void kernel_launch(void* const* d_in, const int* in_sizes, int n_in,
                              void* d_out, int out_size) {
    const float* x      = (const float*)d_in[0];
    const void*  mask   = d_in[1];
    const float* w_qkv  = (const float*)d_in[2];
    const float* w_proj = (const float*)d_in[3];
    const float* b_proj = (const float*)d_in[4];
    float* out = (float*)d_out;

    cudaFuncSetAttribute(attn_kernel, cudaFuncAttributeMaxDynamicSharedMemorySize,
                         ATTN_SMEM_BYTES);

    probe_mask<<<1, 256>>>((const unsigned*)mask);
    mask_pack<<<(NSEQ * (NSEQ / 32) + 255) / 256, 256>>>(mask);
    qkv_gemm<<<dim3(2304 / 128, (BB * NSEQ) / 128), 256>>>(x, w_qkv);
    attn_kernel<<<dim3(NSEQ / 128, BB * HNUM), 128, ATTN_SMEM_BYTES>>>();
    proj_gemm<<<dim3(768 / 128, (BB * NSEQ) / 128), 256>>>(w_proj, b_proj, out);
}

// round 2
// speedup vs baseline: 1.0013x; 1.0013x over previous
#include <cuda_runtime.h>

#define BB 4
#define NSEQ 2048
#define CDIM 768
#define HNUM 12
#define DHEAD 64
#define QK_SCALE 0.125f

// ---------------- scratch (device globals; no allocations allowed) -------
__device__ float g_q[BB * HNUM * NSEQ * DHEAD];
__device__ float g_k[BB * HNUM * NSEQ * DHEAD];
__device__ float g_v[BB * HNUM * NSEQ * DHEAD];
__device__ float g_ctx[BB * NSEQ * CDIM];
__device__ unsigned g_maskbits[NSEQ * (NSEQ / 32)];   // [2048][64] bit-packed
__device__ int g_mask_mode;                            // 0=int32, 1=float32, 2=uint8

// ---------------- mask encoding probe ------------------------------------
__global__ void probe_mask(const unsigned* __restrict__ mw) {
    __shared__ int s_not01, s_notfloat;
    int tid = threadIdx.x;
    if (tid == 0) { s_not01 = 0; s_notfloat = 0; }
    __syncthreads();
    unsigned v = mw[tid];                  // first 256 words (>=1KB always valid)
    if (v != 0u && v != 1u) s_not01 = 1;
    if (v != 0u && v != 0x3F800000u) s_notfloat = 1;
    __syncthreads();
    if (tid == 0) g_mask_mode = (!s_not01) ? 0 : (!s_notfloat ? 1 : 2);
}

__global__ void mask_pack(const void* __restrict__ mask) {
    int gid = blockIdx.x * 256 + threadIdx.x;          // 2048*64 words
    if (gid >= NSEQ * (NSEQ / 32)) return;
    int i = gid >> 6;
    int w = gid & 63;
    long base = (long)i * NSEQ + (long)w * 32;
    int mode = g_mask_mode;
    unsigned bits = 0u;
    if (mode == 0) {
        const int* p = (const int*)mask;
        #pragma unroll
        for (int j = 0; j < 32; j++) if (p[base + j] != 0) bits |= (1u << j);
    } else if (mode == 1) {
        const float* p = (const float*)mask;
        #pragma unroll
        for (int j = 0; j < 32; j++) if (p[base + j] != 0.0f) bits |= (1u << j);
    } else {
        const unsigned char* p = (const unsigned char*)mask;
        #pragma unroll
        for (int j = 0; j < 32; j++) if (p[base + j] != 0) bits |= (1u << j);
    }
    g_maskbits[gid] = bits;
}

// ---------------- GEMM 1: qkv = x @ w_qkv, scatter to q/k/v --------------
// x: [8192, 768], w: [768, 2304]. 128x128 tile, 256 thr, 8x8 per thread.
__global__ __launch_bounds__(256) void qkv_gemm(const float* __restrict__ X,
                                                const float* __restrict__ W) {
    __shared__ float As[8][128];
    __shared__ float Bs[8][128];
    int tid = threadIdx.x;
    int tx = tid & 15, ty = tid >> 4;
    int m0 = blockIdx.y * 128, n0 = blockIdx.x * 128;
    int a_row = tid >> 1, a_k = (tid & 1) * 4;
    int b_row = tid >> 5, b_c = (tid & 31) * 4;
    float acc[8][8];
    #pragma unroll
    for (int i = 0; i < 8; i++)
        #pragma unroll
        for (int j = 0; j < 8; j++) acc[i][j] = 0.0f;

    for (int k0 = 0; k0 < 768; k0 += 8) {
        float4 av = *(const float4*)(X + (long)(m0 + a_row) * 768 + k0 + a_k);
        float4 bv = *(const float4*)(W + (long)(k0 + b_row) * 2304 + n0 + b_c);
        __syncthreads();
        As[a_k + 0][a_row] = av.x;
        As[a_k + 1][a_row] = av.y;
        As[a_k + 2][a_row] = av.z;
        As[a_k + 3][a_row] = av.w;
        *(float4*)&Bs[b_row][b_c] = bv;
        __syncthreads();
        #pragma unroll
        for (int kk = 0; kk < 8; kk++) {
            float a[8], b[8];
            float4 t0 = *(const float4*)&As[kk][ty * 8];
            float4 t1 = *(const float4*)&As[kk][ty * 8 + 4];
            a[0]=t0.x; a[1]=t0.y; a[2]=t0.z; a[3]=t0.w;
            a[4]=t1.x; a[5]=t1.y; a[6]=t1.z; a[7]=t1.w;
            float4 u0 = *(const float4*)&Bs[kk][tx * 8];
            float4 u1 = *(const float4*)&Bs[kk][tx * 8 + 4];
            b[0]=u0.x; b[1]=u0.y; b[2]=u0.z; b[3]=u0.w;
            b[4]=u1.x; b[5]=u1.y; b[6]=u1.z; b[7]=u1.w;
            #pragma unroll
            for (int i = 0; i < 8; i++)
                #pragma unroll
                for (int j = 0; j < 8; j++) acc[i][j] = fmaf(a[i], b[j], acc[i][j]);
        }
    }
    // scatter: n in [0,2304): which = n/768, h = (n%768)/64, d = n%64
    int nb = n0 + tx * 8;                 // 8-aligned -> never crosses 64 boundary
    int which = nb / 768;
    int rem = nb - which * 768;
    int h = rem >> 6;
    int d0 = rem & 63;
    float* dst = (which == 0) ? g_q : ((which == 1) ? g_k : g_v);
    #pragma unroll
    for (int i = 0; i < 8; i++) {
        int m = m0 + ty * 8 + i;
        int b_ = m >> 11, ii = m & 2047;
        float* p = dst + ((((long)b_ * HNUM + h) * NSEQ + ii) * DHEAD + d0);
        *(float4*)p       = make_float4(acc[i][0], acc[i][1], acc[i][2], acc[i][3]);
        *(float4*)(p + 4) = make_float4(acc[i][4], acc[i][5], acc[i][6], acc[i][7]);
    }
}

// ---------------- flash attention -----------------------------------------
// grid: (16 q-tiles, 48 bh). 128 threads, 8x8 micro-tiles.
#define SM_QT 0
#define SM_KT (64 * 132)
#define SM_VS (SM_KT + 64 * 68)
#define SM_PT (SM_VS + 64 * 68)
#define SM_MS (SM_PT + 64 * 132)
#define ATTN_SMEM_BYTES ((SM_MS) * 4 + 128 * 2 * 4)

__global__ __launch_bounds__(128) void attn_kernel() {
    extern __shared__ float sm[];
    float* Qt = sm + SM_QT;     // [64 d][132] rows of 128 queries (+pad)
    float* Kt = sm + SM_KT;     // [64 d][68] keys
    float* Vs = sm + SM_VS;     // [64 key][68] dims
    float* Pt = sm + SM_PT;     // [64 key][132] rows
    unsigned* Ms = (unsigned*)(sm + SM_MS);   // [128 rows][2 words]

    int tid = threadIdx.x;
    int tx = tid & 7, ty = tid >> 3;
    int bh = blockIdx.y;
    int b = bh / HNUM, h = bh - b * HNUM;
    int row0 = blockIdx.x * 128;
    const float* qg = g_q + (long)bh * NSEQ * DHEAD;
    const float* kg = g_k + (long)bh * NSEQ * DHEAD;
    const float* vg = g_v + (long)bh * NSEQ * DHEAD;

    // load Q tile (transposed, pre-scaled)
    #pragma unroll
    for (int r = 0; r < 16; r++) {
        int q4 = r * 128 + tid;
        int row = q4 >> 4;
        int d = (q4 & 15) * 4;
        float4 v = *(const float4*)(qg + (long)(row0 + row) * DHEAD + d);
        Qt[(d + 0) * 132 + row] = v.x * QK_SCALE;
        Qt[(d + 1) * 132 + row] = v.y * QK_SCALE;
        Qt[(d + 2) * 132 + row] = v.z * QK_SCALE;
        Qt[(d + 3) * 132 + row] = v.w * QK_SCALE;
    }

    float O[8][8];
    float mrow[8], lrow[8];
    #pragma unroll
    for (int i = 0; i < 8; i++) {
        mrow[i] = -1e30f; lrow[i] = 0.0f;
        #pragma unroll
        for (int j = 0; j < 8; j++) O[i][j] = 0.0f;
    }

    for (int t = 0; t < 32; t++) {
        int key0 = t * 64;
        __syncthreads();   // previous PV done before overwriting K/V/M
        #pragma unroll
        for (int r = 0; r < 8; r++) {
            int q4 = r * 128 + tid;
            int key = q4 >> 4;
            int d = (q4 & 15) * 4;
            float4 kv = *(const float4*)(kg + (long)(key0 + key) * DHEAD + d);
            Kt[(d + 0) * 68 + key] = kv.x;
            Kt[(d + 1) * 68 + key] = kv.y;
            Kt[(d + 2) * 68 + key] = kv.z;
            Kt[(d + 3) * 68 + key] = kv.w;
            float4 vv = *(const float4*)(vg + (long)(key0 + key) * DHEAD + d);
            *(float4*)&Vs[key * 68 + d] = vv;
        }
        {
            const unsigned* mp = g_maskbits + (long)(row0 + tid) * 64 + t * 2;
            Ms[tid * 2 + 0] = mp[0];
            Ms[tid * 2 + 1] = mp[1];
        }
        __syncthreads();

        // S = Q K^T  (scaled already)
        float s[8][8];
        #pragma unroll
        for (int i = 0; i < 8; i++)
            #pragma unroll
            for (int j = 0; j < 8; j++) s[i][j] = 0.0f;
        #pragma unroll 4
        for (int d = 0; d < 64; d++) {
            float a[8], bv[8];
            float4 t0 = *(const float4*)&Qt[d * 132 + ty * 8];
            float4 t1 = *(const float4*)&Qt[d * 132 + ty * 8 + 4];
            a[0]=t0.x; a[1]=t0.y; a[2]=t0.z; a[3]=t0.w;
            a[4]=t1.x; a[5]=t1.y; a[6]=t1.z; a[7]=t1.w;
            float4 u0 = *(const float4*)&Kt[d * 68 + tx * 8];
            float4 u1 = *(const float4*)&Kt[d * 68 + tx * 8 + 4];
            bv[0]=u0.x; bv[1]=u0.y; bv[2]=u0.z; bv[3]=u0.w;
            bv[4]=u1.x; bv[5]=u1.y; bv[6]=u1.z; bv[7]=u1.w;
            #pragma unroll
            for (int i = 0; i < 8; i++)
                #pragma unroll
                for (int j = 0; j < 8; j++) s[i][j] = fmaf(a[i], bv[j], s[i][j]);
        }

        // mask + online softmax (8 tx-lanes per row group share rows; same warp)
        int wsel = (tx >> 2) & 1;
        int bit0 = (tx & 3) * 8;
        #pragma unroll
        for (int i = 0; i < 8; i++) {
            unsigned mw = Ms[(ty * 8 + i) * 2 + wsel];
            float tmax = -1e30f;
            #pragma unroll
            for (int j = 0; j < 8; j++) {
                if ((mw >> (bit0 + j)) & 1u) s[i][j] = -1e30f;
                tmax = fmaxf(tmax, s[i][j]);
            }
            tmax = fmaxf(tmax, __shfl_xor_sync(0xffffffffu, tmax, 1));
            tmax = fmaxf(tmax, __shfl_xor_sync(0xffffffffu, tmax, 2));
            tmax = fmaxf(tmax, __shfl_xor_sync(0xffffffffu, tmax, 4));
            float mnew = fmaxf(mrow[i], tmax);
            float alpha = __expf(mrow[i] - mnew);
            mrow[i] = mnew;
            float lsum = 0.0f;
            #pragma unroll
            for (int j = 0; j < 8; j++) {
                float p = __expf(s[i][j] - mnew);
                s[i][j] = p;
                lsum += p;
            }
            lsum += __shfl_xor_sync(0xffffffffu, lsum, 1);
            lsum += __shfl_xor_sync(0xffffffffu, lsum, 2);
            lsum += __shfl_xor_sync(0xffffffffu, lsum, 4);
            lrow[i] = lrow[i] * alpha + lsum;
            #pragma unroll
            for (int j = 0; j < 8; j++) O[i][j] *= alpha;
        }

        // stage P transposed for the PV GEMM
        #pragma unroll
        for (int j = 0; j < 8; j++)
            #pragma unroll
            for (int i = 0; i < 8; i++)
                Pt[(tx * 8 + j) * 132 + ty * 8 + i] = s[i][j];
        __syncthreads();

        // O += P @ V
        #pragma unroll 4
        for (int k = 0; k < 64; k++) {
            float a[8], bv[8];
            float4 t0 = *(const float4*)&Pt[k * 132 + ty * 8];
            float4 t1 = *(const float4*)&Pt[k * 132 + ty * 8 + 4];
            a[0]=t0.x; a[1]=t0.y; a[2]=t0.z; a[3]=t0.w;
            a[4]=t1.x; a[5]=t1.y; a[6]=t1.z; a[7]=t1.w;
            float4 u0 = *(const float4*)&Vs[k * 68 + tx * 8];
            float4 u1 = *(const float4*)&Vs[k * 68 + tx * 8 + 4];
            bv[0]=u0.x; bv[1]=u0.y; bv[2]=u0.z; bv[3]=u0.w;
            bv[4]=u1.x; bv[5]=u1.y; bv[6]=u1.z; bv[7]=u1.w;
            #pragma unroll
            for (int i = 0; i < 8; i++)
                #pragma unroll
                for (int j = 0; j < 8; j++) O[i][j] = fmaf(a[i], bv[j], O[i][j]);
        }
    }

    // epilogue: normalize, write to ctx in [B, N, C] layout
    #pragma unroll
    for (int i = 0; i < 8; i++) {
        float inv = 1.0f / lrow[i];
        int row = row0 + ty * 8 + i;
        float* dst = g_ctx + ((long)b * NSEQ + row) * CDIM + h * DHEAD + tx * 8;
        *(float4*)dst       = make_float4(O[i][0]*inv, O[i][1]*inv, O[i][2]*inv, O[i][3]*inv);
        *(float4*)(dst + 4) = make_float4(O[i][4]*inv, O[i][5]*inv, O[i][6]*inv, O[i][7]*inv);
    }
}

// ---------------- GEMM 2: out = ctx @ w_proj + b_proj ---------------------
__global__ __launch_bounds__(256) void proj_gemm(const float* __restrict__ W,
                                                 const float* __restrict__ Bias,
                                                 float* __restrict__ Out) {
    __shared__ float As[8][128];
    __shared__ float Bs[8][128];
    int tid = threadIdx.x;
    int tx = tid & 15, ty = tid >> 4;
    int m0 = blockIdx.y * 128, n0 = blockIdx.x * 128;
    int a_row = tid >> 1, a_k = (tid & 1) * 4;
    int b_row = tid >> 5, b_c = (tid & 31) * 4;
    float acc[8][8];
    #pragma unroll
    for (int i = 0; i < 8; i++)
        #pragma unroll
        for (int j = 0; j < 8; j++) acc[i][j] = 0.0f;

    for (int k0 = 0; k0 < 768; k0 += 8) {
        float4 av = *(const float4*)(g_ctx + (long)(m0 + a_row) * 768 + k0 + a_k);
        float4 bv = *(const float4*)(W + (long)(k0 + b_row) * 768 + n0 + b_c);
        __syncthreads();
        As[a_k + 0][a_row] = av.x;
        As[a_k + 1][a_row] = av.y;
        As[a_k + 2][a_row] = av.z;
        As[a_k + 3][a_row] = av.w;
        *(float4*)&Bs[b_row][b_c] = bv;
        __syncthreads();
        #pragma unroll
        for (int kk = 0; kk < 8; kk++) {
            float a[8], b[8];
            float4 t0 = *(const float4*)&As[kk][ty * 8];
            float4 t1 = *(const float4*)&As[kk][ty * 8 + 4];
            a[0]=t0.x; a[1]=t0.y; a[2]=t0.z; a[3]=t0.w;
            a[4]=t1.x; a[5]=t1.y; a[6]=t1.z; a[7]=t1.w;
            float4 u0 = *(const float4*)&Bs[kk][tx * 8];
            float4 u1 = *(const float4*)&Bs[kk][tx * 8 + 4];
            b[0]=u0.x; b[1]=u0.y; b[2]=u0.z; b[3]=u0.w;
            b[4]=u1.x; b[5]=u1.y; b[6]=u1.z; b[7]=u1.w;
            #pragma unroll
            for (int i = 0; i < 8; i++)
                #pragma unroll
                for (int j = 0; j < 8; j++) acc[i][j] = fmaf(a[i], b[j], acc[i][j]);
        }
    }
    float bj[8];
    #pragma unroll
    for (int j = 0; j < 8; j++) bj[j] = Bias[n0 + tx * 8 + j];
    #pragma unroll
    for (int i = 0; i < 8; i++) {
        int m = m0 + ty * 8 + i;
        float* p = Out + (long)m * 768 + n0 + tx * 8;
        *(float4*)p       = make_float4(acc[i][0]+bj[0], acc[i][1]+bj[1],
                                        acc[i][2]+bj[2], acc[i][3]+bj[3]);
        *(float4*)(p + 4) = make_float4(acc[i][4]+bj[4], acc[i][5]+bj[5],
                                        acc[i][6]+bj[6], acc[i][7]+bj[7]);
    }
}

// ---------------- launch ---------------------------------------------------
extern "C" void kernel_launch(void* const* d_in, const int* in_sizes, int n_in,
                              void* d_out, int out_size) {
    const float* x      = (const float*)d_in[0];
    const void*  mask   = d_in[1];
    const float* w_qkv  = (const float*)d_in[2];
    const float* w_proj = (const float*)d_in[3];
    const float* b_proj = (const float*)d_in[4];
    float* out = (float*)d_out;

    cudaFuncSetAttribute(attn_kernel, cudaFuncAttributeMaxDynamicSharedMemorySize,
                         ATTN_SMEM_BYTES);

    probe_mask<<<1, 256>>>((const unsigned*)mask);
    mask_pack<<<(NSEQ * (NSEQ / 32) + 255) / 256, 256>>>(mask);
    qkv_gemm<<<dim3(2304 / 128, (BB * NSEQ) / 128), 256>>>(x, w_qkv);
    attn_kernel<<<dim3(NSEQ / 128, BB * HNUM), 128, ATTN_SMEM_BYTES>>>();
    proj_gemm<<<dim3(768 / 128, (BB * NSEQ) / 128), 256>>>(w_proj, b_proj, out);
}